// round 4
// baseline (speedup 1.0000x reference)
#include <cuda_runtime.h>
#include <cuda_bf16.h>

#define NPARAMS 1280

// out[i] = Param_b[b_params[i]]   (also serves as the zero-init for the scatter)
__global__ void bias_init_kernel(const float* __restrict__ Pb,
                                 const int*   __restrict__ bidx,
                                 float*       __restrict__ out,
                                 int n) {
    int i = blockIdx.x * blockDim.x + threadIdx.x;
    if (i < n) {
        out[i] = __ldg(&Pb[__ldg(&bidx[i])]);
    }
}

// For each edge e: out[rows[e]] += Param_W[params[e]] * x[cols[e]]
// Vectorized 4 edges per thread per grid-stride iteration.
__global__ void edge_scatter_kernel(const float* __restrict__ x,
                                    const float* __restrict__ Pw,
                                    const int*   __restrict__ rows,
                                    const int*   __restrict__ cols,
                                    const int*   __restrict__ params,
                                    float*       __restrict__ out,
                                    int nvec,   // E / 4
                                    int tail,   // E % 4
                                    int E) {
    __shared__ float sPw[NPARAMS];
    for (int i = threadIdx.x; i < NPARAMS; i += blockDim.x)
        sPw[i] = Pw[i];
    __syncthreads();

    const int4* __restrict__ rows4   = (const int4*)rows;
    const int4* __restrict__ cols4   = (const int4*)cols;
    const int4* __restrict__ params4 = (const int4*)params;

    int gtid   = blockIdx.x * blockDim.x + threadIdx.x;
    int stride = gridDim.x * blockDim.x;

    for (int v = gtid; v < nvec; v += stride) {
        int4 r = rows4[v];
        int4 c = cols4[v];
        int4 p = params4[v];

        float x0 = __ldg(&x[c.x]);
        float x1 = __ldg(&x[c.y]);
        float x2 = __ldg(&x[c.z]);
        float x3 = __ldg(&x[c.w]);

        float v0 = sPw[p.x] * x0;
        float v1 = sPw[p.y] * x1;
        float v2 = sPw[p.z] * x2;
        float v3 = sPw[p.w] * x3;

        atomicAdd(&out[r.x], v0);
        atomicAdd(&out[r.y], v1);
        atomicAdd(&out[r.z], v2);
        atomicAdd(&out[r.w], v3);
    }

    // Tail edges (E not divisible by 4) — defensive, E = 2^24 here.
    if (gtid < tail) {
        int e = E - tail + gtid;
        float val = sPw[params[e]] * __ldg(&x[cols[e]]);
        atomicAdd(&out[rows[e]], val);
    }
}

extern "C" void kernel_launch(void* const* d_in, const int* in_sizes, int n_in,
                              void* d_out, int out_size) {
    // metadata order: x, Param_W, Param_b, w_rows, w_cols, w_params, b_params
    const float* x        = (const float*)d_in[0];
    const float* Param_W  = (const float*)d_in[1];
    const float* Param_b  = (const float*)d_in[2];
    const int*   w_rows   = (const int*)d_in[3];
    const int*   w_cols   = (const int*)d_in[4];
    const int*   w_params = (const int*)d_in[5];
    const int*   b_params = (const int*)d_in[6];
    float*       out      = (float*)d_out;

    const int N = out_size;         // 262144
    const int E = in_sizes[3];      // 16777216

    // 1) bias init (also zero-init for the scatter)
    {
        int threads = 256;
        int blocks  = (N + threads - 1) / threads;
        bias_init_kernel<<<blocks, threads>>>(Param_b, b_params, out, N);
    }

    // 2) edge scatter
    {
        int nvec = E / 4;
        int tail = E - nvec * 4;
        int threads = 256;
        // 152 SMs x 8 resident CTAs (2048-thread limit / 256) -> one full wave,
        // grid-stride covers the rest; keeps Param_W smem fills amortized.
        int blocks = 152 * 8;
        edge_scatter_kernel<<<blocks, threads>>>(x, Param_W, w_rows, w_cols,
                                                 w_params, out, nvec, tail, E);
    }
}